// round 15
// baseline (speedup 1.0000x reference)
#include <cuda_runtime.h>
#include <cuda_bf16.h>
#include <math.h>
#include <stdint.h>

// Problem constants
#define S_LEN 2048
#define HID   2048
#define NH    32
#define KVH   8
#define HD    64
#define GQ    4
#define QKV_N 3072

// Scratch
__device__ float g_qkv[S_LEN * QKV_N];
__device__ float g_attn[S_LEN * HID];

// ---------------------------------------------------------------------------
// 3xTF32 tensor-core GEMM NT: C[M,N] = A[M,K] * B[N,K]^T
// CTA tile 128x128, BK=16, 256 threads = 8 warps (2 m x 4 n), warp tile 64x32.
// mma.m16n8k8 tf32, hi/lo split in registers for fp32-grade accuracy.
// ---------------------------------------------------------------------------
#define BM 128
#define BN 128
#define BK 16
#define SSTR 20   // smem row stride (16 + 4 pad) -> conflict-free frag loads

__device__ __forceinline__ uint32_t f2tf32(float x) {
    uint32_t r;
    asm("cvt.rna.tf32.f32 %0, %1;" : "=r"(r) : "f"(x));
    return r;
}

__device__ __forceinline__ void mma_tf32(float4& d,
    uint32_t a0, uint32_t a1, uint32_t a2, uint32_t a3,
    uint32_t b0, uint32_t b1)
{
    asm volatile(
        "mma.sync.aligned.m16n8k8.row.col.f32.tf32.tf32.f32 "
        "{%0,%1,%2,%3}, {%4,%5,%6,%7}, {%8,%9}, {%0,%1,%2,%3};"
        : "+f"(d.x), "+f"(d.y), "+f"(d.z), "+f"(d.w)
        : "r"(a0), "r"(a1), "r"(a2), "r"(a3), "r"(b0), "r"(b1));
}

__global__ __launch_bounds__(256) void gemm_tf32_nt(
    const float* __restrict__ A, const float* __restrict__ B,
    float* __restrict__ C, int M, int N, int K)
{
    __shared__ float As[BM][SSTR];
    __shared__ float Bs[BN][SSTR];

    const int m0 = blockIdx.y * BM;
    const int n0 = blockIdx.x * BN;
    const int tid  = threadIdx.x;
    const int lane = tid & 31;
    const int wid  = tid >> 5;
    const int wm   = wid & 1;          // 0..1 -> 64 rows each
    const int wn   = wid >> 1;         // 0..3 -> 32 cols each
    const int grp  = lane >> 2;        // 0..7
    const int tig  = lane & 3;         // 0..3

    float4 acc[4][4];
#pragma unroll
    for (int i = 0; i < 4; i++)
#pragma unroll
        for (int j = 0; j < 4; j++) acc[i][j] = make_float4(0.f, 0.f, 0.f, 0.f);

    // Per-thread fragment base pointers
    const float* abase = &As[wm * 64 + grp][tig];
    const float* bbase = &Bs[wn * 32 + grp][tig];

    for (int k0 = 0; k0 < K; k0 += BK) {
        // ---- Stage A,B tiles (natural [row][k] layout, float4 copies) ----
#pragma unroll
        for (int l = 0; l < 2; l++) {
            int idx = tid + l * 256;          // 0..511
            int row = idx >> 2;               // 0..127
            int kg  = (idx & 3) << 2;         // 0,4,8,12
            *(float4*)&As[row][kg] = *(const float4*)&A[(size_t)(m0 + row) * K + k0 + kg];
            *(float4*)&Bs[row][kg] = *(const float4*)&B[(size_t)(n0 + row) * K + k0 + kg];
        }
        __syncthreads();

#pragma unroll
        for (int ks = 0; ks < BK; ks += 8) {
            // ---- Load + split A fragments (4 m-frags) ----
            uint32_t ah[4][4], al[4][4];
#pragma unroll
            for (int mf = 0; mf < 4; mf++) {
                const float* ap = abase + mf * (16 * SSTR) + ks;
                float x0 = ap[0];
                float x1 = ap[8 * SSTR];
                float x2 = ap[4];
                float x3 = ap[8 * SSTR + 4];
                ah[mf][0] = f2tf32(x0); al[mf][0] = f2tf32(x0 - __uint_as_float(ah[mf][0]));
                ah[mf][1] = f2tf32(x1); al[mf][1] = f2tf32(x1 - __uint_as_float(ah[mf][1]));
                ah[mf][2] = f2tf32(x2); al[mf][2] = f2tf32(x2 - __uint_as_float(ah[mf][2]));
                ah[mf][3] = f2tf32(x3); al[mf][3] = f2tf32(x3 - __uint_as_float(ah[mf][3]));
            }
            // ---- Load + split B fragments (4 n-frags) ----
            uint32_t bh[4][2], bl[4][2];
#pragma unroll
            for (int nf = 0; nf < 4; nf++) {
                const float* bp = bbase + nf * (8 * SSTR) + ks;
                float y0 = bp[0];
                float y1 = bp[4];
                bh[nf][0] = f2tf32(y0); bl[nf][0] = f2tf32(y0 - __uint_as_float(bh[nf][0]));
                bh[nf][1] = f2tf32(y1); bl[nf][1] = f2tf32(y1 - __uint_as_float(bh[nf][1]));
            }
            // ---- 3xTF32 MMAs ----
#pragma unroll
            for (int mf = 0; mf < 4; mf++) {
#pragma unroll
                for (int nf = 0; nf < 4; nf++) {
                    mma_tf32(acc[mf][nf], ah[mf][0], ah[mf][1], ah[mf][2], ah[mf][3],
                             bh[nf][0], bh[nf][1]);
                    mma_tf32(acc[mf][nf], al[mf][0], al[mf][1], al[mf][2], al[mf][3],
                             bh[nf][0], bh[nf][1]);
                    mma_tf32(acc[mf][nf], ah[mf][0], ah[mf][1], ah[mf][2], ah[mf][3],
                             bl[nf][0], bl[nf][1]);
                }
            }
        }
        __syncthreads();
    }

    // ---- Writeback: c0,c1 at (row, 2*tig), c2,c3 at (row+8, 2*tig) ----
#pragma unroll
    for (int mf = 0; mf < 4; mf++) {
        int r = m0 + wm * 64 + mf * 16 + grp;
#pragma unroll
        for (int nf = 0; nf < 4; nf++) {
            int c = n0 + wn * 32 + nf * 8 + 2 * tig;
            *(float2*)&C[(size_t)r * N + c]       = make_float2(acc[mf][nf].x, acc[mf][nf].y);
            *(float2*)&C[(size_t)(r + 8) * N + c] = make_float2(acc[mf][nf].z, acc[mf][nf].w);
        }
    }
}

// ---------------------------------------------------------------------------
// RoPE (in place on Q heads 0..31 and K heads 32..39 of g_qkv)
// ---------------------------------------------------------------------------
__global__ void rope_kernel(float* __restrict__ qkv)
{
    int idx = blockIdx.x * blockDim.x + threadIdx.x;
    const int total = S_LEN * (NH + KVH) * (HD / 2);
    if (idx >= total) return;

    int i  = idx & 31;
    int hh = (idx >> 5) % (NH + KVH);
    int s  = idx / ((NH + KVH) * 32);

    double ifd = exp(-9.210340371976184 * (double)i / 32.0);
    float inv_freq = (float)ifd;
    float fr = (float)s * inv_freq;
    float c = cosf(fr);
    float sn = sinf(fr);

    size_t base = (size_t)s * QKV_N +
                  (hh < NH ? hh * HD : NH * HD + (hh - NH) * HD);
    float x1 = qkv[base + i];
    float x2 = qkv[base + 32 + i];
    qkv[base + i]      = x1 * c - x2 * sn;
    qkv[base + 32 + i] = x2 * c + x1 * sn;
}

// ---------------------------------------------------------------------------
// Flash attention, GEMM-tiled (unchanged from R14).
// ---------------------------------------------------------------------------
#define QT 64
#define KT 32
#define PS_STRIDE 68

__global__ __launch_bounds__(256) void attn_kernel(
    const float* __restrict__ qkv, float* __restrict__ attn_out)
{
    const int h   = blockIdx.y;
    const int kvh = h >> 2;
    const int qt  = gridDim.x - 1 - blockIdx.x;
    const int tid = threadIdx.x;
    const int tx  = tid & 15;
    const int ty  = tid >> 4;

    __shared__ float Qs[HD][QT];
    __shared__ float Ks[HD][KT];
    __shared__ float Vs[KT][HD];
    __shared__ float Ps[KT][PS_STRIDE];

#pragma unroll
    for (int l = 0; l < 4; l++) {
        int f  = tid + l * 256;
        int q  = f & 63;
        int d4 = (f >> 6) * 4;
        float4 v = *(const float4*)&qkv[(size_t)(qt * QT + q) * QKV_N + h * HD + d4];
        Qs[d4 + 0][q] = v.x * 0.125f;
        Qs[d4 + 1][q] = v.y * 0.125f;
        Qs[d4 + 2][q] = v.z * 0.125f;
        Qs[d4 + 3][q] = v.w * 0.125f;
    }

    float4 o4[4];
#pragma unroll
    for (int i = 0; i < 4; i++) o4[i] = make_float4(0.f, 0.f, 0.f, 0.f);
    float m[4], l[4];
#pragma unroll
    for (int i = 0; i < 4; i++) { m[i] = -1e30f; l[i] = 0.f; }

    const int ntiles = 2 * qt + 2;
    for (int kt = 0; kt < ntiles; kt++) {
        __syncthreads();
#pragma unroll
        for (int ll = 0; ll < 2; ll++) {
            int f  = tid + ll * 256;
            int t  = f & 31;
            int d4 = (f >> 5) * 4;
            float4 v = *(const float4*)&qkv[(size_t)(kt * KT + t) * QKV_N
                                            + NH * HD + kvh * HD + d4];
            Ks[d4 + 0][t] = v.x;
            Ks[d4 + 1][t] = v.y;
            Ks[d4 + 2][t] = v.z;
            Ks[d4 + 3][t] = v.w;
        }
#pragma unroll
        for (int ll = 0; ll < 2; ll++) {
            int f  = tid + ll * 256;
            int t  = f >> 4;
            int d4 = (f & 15) * 4;
            *(float4*)&Vs[t][d4] = *(const float4*)&qkv[(size_t)(kt * KT + t) * QKV_N
                                                        + (NH + KVH) * HD + kvh * HD + d4];
        }
        __syncthreads();

        float sc[4][2];
#pragma unroll
        for (int i = 0; i < 4; i++) { sc[i][0] = 0.f; sc[i][1] = 0.f; }

#pragma unroll 8
        for (int d = 0; d < HD; d++) {
            float4 qv = *(const float4*)&Qs[d][ty * 4];
            float2 kv = *(const float2*)&Ks[d][tx * 2];
            sc[0][0] = fmaf(qv.x, kv.x, sc[0][0]);
            sc[0][1] = fmaf(qv.x, kv.y, sc[0][1]);
            sc[1][0] = fmaf(qv.y, kv.x, sc[1][0]);
            sc[1][1] = fmaf(qv.y, kv.y, sc[1][1]);
            sc[2][0] = fmaf(qv.z, kv.x, sc[2][0]);
            sc[2][1] = fmaf(qv.z, kv.y, sc[2][1]);
            sc[3][0] = fmaf(qv.w, kv.x, sc[3][0]);
            sc[3][1] = fmaf(qv.w, kv.y, sc[3][1]);
        }

        if (kt * KT + KT - 1 > qt * QT) {
#pragma unroll
            for (int i = 0; i < 4; i++) {
                int gq = qt * QT + ty * 4 + i;
#pragma unroll
                for (int j = 0; j < 2; j++) {
                    int gk = kt * KT + tx * 2 + j;
                    if (gk > gq) sc[i][j] = -1e30f;
                }
            }
        }

#pragma unroll
        for (int i = 0; i < 4; i++) {
            float rm = fmaxf(sc[i][0], sc[i][1]);
#pragma unroll
            for (int s = 1; s < 16; s <<= 1)
                rm = fmaxf(rm, __shfl_xor_sync(0xffffffffu, rm, s));
            float mnew = fmaxf(m[i], rm);
            float alpha = __expf(m[i] - mnew);
            float p0 = __expf(sc[i][0] - mnew);
            float p1 = __expf(sc[i][1] - mnew);
            sc[i][0] = p0; sc[i][1] = p1;
            float rs = p0 + p1;
#pragma unroll
            for (int s = 1; s < 16; s <<= 1)
                rs += __shfl_xor_sync(0xffffffffu, rs, s);
            l[i] = l[i] * alpha + rs;
            m[i] = mnew;
            o4[i].x *= alpha; o4[i].y *= alpha;
            o4[i].z *= alpha; o4[i].w *= alpha;
        }

#pragma unroll
        for (int j = 0; j < 2; j++) {
            float4 pv = make_float4(sc[0][j], sc[1][j], sc[2][j], sc[3][j]);
            *(float4*)&Ps[tx * 2 + j][ty * 4] = pv;
        }
        __syncthreads();

#pragma unroll 4
        for (int k = 0; k < KT; k++) {
            float4 pv = *(const float4*)&Ps[k][ty * 4];
            float4 vv = *(const float4*)&Vs[k][tx * 4];
            o4[0].x = fmaf(pv.x, vv.x, o4[0].x);
            o4[0].y = fmaf(pv.x, vv.y, o4[0].y);
            o4[0].z = fmaf(pv.x, vv.z, o4[0].z);
            o4[0].w = fmaf(pv.x, vv.w, o4[0].w);
            o4[1].x = fmaf(pv.y, vv.x, o4[1].x);
            o4[1].y = fmaf(pv.y, vv.y, o4[1].y);
            o4[1].z = fmaf(pv.y, vv.z, o4[1].z);
            o4[1].w = fmaf(pv.y, vv.w, o4[1].w);
            o4[2].x = fmaf(pv.z, vv.x, o4[2].x);
            o4[2].y = fmaf(pv.z, vv.y, o4[2].y);
            o4[2].z = fmaf(pv.z, vv.z, o4[2].z);
            o4[2].w = fmaf(pv.z, vv.w, o4[2].w);
            o4[3].x = fmaf(pv.w, vv.x, o4[3].x);
            o4[3].y = fmaf(pv.w, vv.y, o4[3].y);
            o4[3].z = fmaf(pv.w, vv.z, o4[3].z);
            o4[3].w = fmaf(pv.w, vv.w, o4[3].w);
        }
    }

#pragma unroll
    for (int i = 0; i < 4; i++) {
        float inv = 1.f / l[i];
        float4 v = o4[i];
        v.x *= inv; v.y *= inv; v.z *= inv; v.w *= inv;
        *(float4*)&attn_out[(size_t)(qt * QT + ty * 4 + i) * HID + h * HD + tx * 4] = v;
    }
}

// ---------------------------------------------------------------------------
// Launch
// ---------------------------------------------------------------------------
extern "C" void kernel_launch(void* const* d_in, const int* in_sizes, int n_in,
                              void* d_out, int out_size)
{
    const float* x     = (const float*)d_in[0];
    const float* w_qkv = (const float*)d_in[1];
    const float* w_o   = (const float*)d_in[2];
    float* out = (float*)d_out;

    float* qkv_buf = nullptr;
    float* attn_buf = nullptr;
    cudaGetSymbolAddress((void**)&qkv_buf, g_qkv);
    cudaGetSymbolAddress((void**)&attn_buf, g_attn);

    // 1) QKV projection (tensor-core 3xTF32)
    {
        dim3 grid(QKV_N / BN, S_LEN / BM);
        gemm_tf32_nt<<<grid, 256>>>(x, w_qkv, qkv_buf, S_LEN, QKV_N, HID);
    }

    // 2) RoPE in place
    {
        int total = S_LEN * (NH + KVH) * (HD / 2);
        rope_kernel<<<(total + 255) / 256, 256>>>(qkv_buf);
    }

    // 3) Causal GQA attention
    {
        dim3 grid(S_LEN / QT, NH);
        attn_kernel<<<grid, 256>>>(qkv_buf, attn_buf);
    }

    // 4) Output projection (tensor-core 3xTF32)
    {
        dim3 grid(HID / BN, S_LEN / BM);
        gemm_tf32_nt<<<grid, 256>>>(attn_buf, w_o, out, S_LEN, HID, HID);
    }
}